// round 5
// baseline (speedup 1.0000x reference)
#include <cuda_runtime.h>
#include <cuda_fp16.h>
#include <cstdint>

#define N_ATOMS 100000
#define EDGES   400000
#define BGR     1024
#define FXD     78
#define DIM     32
#define OUTD    128
#define EMBD    128
#define VOCAB   26
#define NFLT    32
#define SEQ     1000
#define KW      8
#define CONVL   993           // SEQ - KW + 1
#define FLAT    31776         // NFLT * CONVL
#define COMB    2304          // 2*OUTD + 2*1024
#define H1DIM   1024
#define H2DIM   256
#define LMDIM   1024
#define NB_SCAN ((N_ATOMS + 255) / 256)   // 391

#define SPLITS_XT 37
#define CPS_XT    27          // 37*27 = 999 >= 993 chunks (1 chunk = 1 tpos)
#define TOKSLAB   (CPS_XT + 7)  // 34 tokens per protein per split

// ------------------------- scratch (device globals) -------------------------
__device__ float g_p[N_ATOMS * DIM];
__device__ float g_y[N_ATOMS * DIM];
__device__ float g_stats[5 * 2 * DIM];
__device__ float g_bn[2 * DIM];
__device__ float g_xg[BGR * DIM];
__device__ float g_lut[KW * NFLT * VOCAB];

// CSR scratch
__device__ int g_deg[N_ATOMS];
__device__ int g_rowptr[N_ATOMS + 1];
__device__ int g_cur[N_ATOMS];
__device__ int g_esorted[EDGES];
__device__ int g_blocksum[512];

// fp16 hi/lo weight & activation buffers
__device__ __half g_BxtH[(size_t)OUTD * FLAT];   // fc1_xt_w reordered+T
__device__ __half g_BxtL[(size_t)OUTD * FLAT];
__device__ __half g_B1H[(size_t)H1DIM * COMB];   // fc1_w^T
__device__ __half g_B1L[(size_t)H1DIM * COMB];
__device__ __half g_B2H[(size_t)H2DIM * H1DIM];  // fc2_w^T
__device__ __half g_B2L[(size_t)H2DIM * H1DIM];
__device__ __half g_XCh[(size_t)BGR * COMB];
__device__ __half g_XCl[(size_t)BGR * COMB];
__device__ __half g_H1h[(size_t)BGR * H1DIM];
__device__ __half g_H1l[(size_t)BGR * H1DIM];

__device__ float g_xtacc[BGR * OUTD];
__device__ float g_h1acc[BGR * H1DIM];
__device__ float g_h2acc[BGR * H2DIM];
__device__ float g_h2[BGR * H2DIM];

__device__ __forceinline__ void split16(float v, __half& h, __half& l) {
    h = __float2half_rn(v);
    l = __float2half_rn(v - __half2float(h));
}

// ------------------------------- zero scratch -------------------------------
__global__ void zero_kernel() {
    int idx = blockIdx.x * blockDim.x + threadIdx.x;
    int stride = gridDim.x * blockDim.x;
    for (int i = idx; i < BGR * OUTD; i += stride) g_xtacc[i] = 0.f;
    for (int i = idx; i < BGR * H1DIM; i += stride) g_h1acc[i] = 0.f;
    for (int i = idx; i < BGR * H2DIM; i += stride) g_h2acc[i] = 0.f;
    for (int i = idx; i < BGR * DIM; i += stride) g_xg[i] = 0.f;
    for (int i = idx; i < 5 * 2 * DIM; i += stride) g_stats[i] = 0.f;
    for (int i = idx; i < N_ATOMS; i += stride) g_deg[i] = 0;
}

// ----------------------------- CSR construction -----------------------------
__global__ void hist_kernel(const int* __restrict__ dst) {
    int e = blockIdx.x * blockDim.x + threadIdx.x;
    if (e < EDGES) atomicAdd(&g_deg[dst[e]], 1);
}

__global__ void scan1_kernel() {
    __shared__ int s[256];
    int tid = threadIdx.x;
    int i = blockIdx.x * 256 + tid;
    int v = (i < N_ATOMS) ? g_deg[i] : 0;
    s[tid] = v;
    __syncthreads();
#pragma unroll
    for (int o = 1; o < 256; o <<= 1) {
        int u = (tid >= o) ? s[tid - o] : 0;
        __syncthreads();
        s[tid] += u;
        __syncthreads();
    }
    if (i < N_ATOMS) g_rowptr[i] = s[tid] - v;
    if (tid == 255) g_blocksum[blockIdx.x] = s[255];
}

__global__ void scan2_kernel() {
    __shared__ int s[512];
    int tid = threadIdx.x;
    int v = (tid < NB_SCAN) ? g_blocksum[tid] : 0;
    s[tid] = v;
    __syncthreads();
#pragma unroll
    for (int o = 1; o < 512; o <<= 1) {
        int u = (tid >= o) ? s[tid - o] : 0;
        __syncthreads();
        s[tid] += u;
        __syncthreads();
    }
    if (tid < NB_SCAN) g_blocksum[tid] = s[tid] - v;
}

__global__ void scan3_kernel() {
    int i = blockIdx.x * blockDim.x + threadIdx.x;
    if (i < N_ATOMS) {
        int v = g_rowptr[i] + g_blocksum[i >> 8];
        g_rowptr[i] = v;
        g_cur[i] = v;
    }
    if (i == 0) g_rowptr[N_ATOMS] = EDGES;
}

__global__ void scatter_kernel(const int* __restrict__ src, const int* __restrict__ dst) {
    int e = blockIdx.x * blockDim.x + threadIdx.x;
    if (e >= EDGES) return;
    int pos = atomicAdd(&g_cur[dst[e]], 1);
    g_esorted[pos] = src[e];
}

// -------------- weight transpose + fp16 split: W[K][N] -> Bt[N][K] ----------
__global__ void w16t_kernel(const float* __restrict__ W,
                            __half* __restrict__ Bh, __half* __restrict__ Bl,
                            int K, int N)
{
    __shared__ float ts[32][33];
    int k0 = blockIdx.x * 32, n0 = blockIdx.y * 32;
    int tx = threadIdx.x & 31, ty = threadIdx.x >> 5;
#pragma unroll
    for (int i = 0; i < 4; i++)
        ts[ty + i * 8][tx] = W[(size_t)(k0 + ty + i * 8) * N + n0 + tx];
    __syncthreads();
#pragma unroll
    for (int i = 0; i < 4; i++) {
        int n = ty + i * 8;
        float v = ts[tx][n];
        __half h, l; split16(v, h, l);
        size_t o = (size_t)(n0 + n) * K + k0 + tx;
        Bh[o] = h; Bl[o] = l;
    }
}

// ------ fc1_xt weight: reorder K (f*993+t -> t*32+f), transpose, split ------
__global__ void w16tx_kernel(const float* __restrict__ W,
                             __half* __restrict__ Bh, __half* __restrict__ Bl)
{
    __shared__ float ts[32][33];
    int t = blockIdx.x;             // tpos 0..992; k0 = t*32
    int n0 = blockIdx.y * 32;
    int tx = threadIdx.x & 31, ty = threadIdx.x >> 5;
#pragma unroll
    for (int i = 0; i < 4; i++) {
        int f = ty + i * 8;         // kk within tile = filter index
        ts[f][tx] = W[(size_t)(f * CONVL + t) * OUTD + n0 + tx];
    }
    __syncthreads();
#pragma unroll
    for (int i = 0; i < 4; i++) {
        int n = ty + i * 8;
        float v = ts[tx][n];
        __half h, l; split16(v, h, l);
        size_t o = (size_t)(n0 + n) * FLAT + t * 32 + tx;
        Bh[o] = h; Bl[o] = l;
    }
}

// =========================== fp16x3 MMA helpers ==============================
#define ASTR 40   // smem row stride in halfs (80B -> conflict-free ldmatrix)

__device__ __forceinline__ uint32_t smem_u32(const void* p) {
    uint32_t a;
    asm("{ .reg .u64 t; cvta.to.shared.u64 t, %1; cvt.u32.u64 %0, t; }"
        : "=r"(a) : "l"(p));
    return a;
}
__device__ __forceinline__ void ldm4(uint32_t* r, uint32_t saddr) {
    asm volatile("ldmatrix.sync.aligned.m8n8.x4.shared.b16 {%0,%1,%2,%3}, [%4];"
        : "=r"(r[0]), "=r"(r[1]), "=r"(r[2]), "=r"(r[3]) : "r"(saddr));
}
__device__ __forceinline__ void mma16816(float* d, const uint32_t* a,
                                         uint32_t b0, uint32_t b1) {
    asm volatile(
        "mma.sync.aligned.m16n8k16.row.col.f32.f16.f16.f32 "
        "{%0,%1,%2,%3}, {%4,%5,%6,%7}, {%8,%9}, {%0,%1,%2,%3};"
        : "+f"(d[0]), "+f"(d[1]), "+f"(d[2]), "+f"(d[3])
        : "r"(a[0]), "r"(a[1]), "r"(a[2]), "r"(a[3]), "r"(b0), "r"(b1));
}

// ============================ generic hgemm ==================================
__global__ void __launch_bounds__(256, 2) hgemm(
    const __half* __restrict__ Ah, const __half* __restrict__ Al,
    const __half* __restrict__ Bh, const __half* __restrict__ Bl,
    float* __restrict__ Cacc, int lda, int ldb, int ldc,
    int totalChunks, int chunksPerSplit)
{
    __shared__ __half sAh[128 * ASTR], sAl[128 * ASTR];
    __shared__ __half sBh[128 * ASTR], sBl[128 * ASTR];

    int tid = threadIdx.x, lane = tid & 31, wid = tid >> 5;
    int mw = wid & 3, nw = wid >> 2;
    int m0 = blockIdx.y * 128, n0 = blockIdx.x * 128;

    int c0 = blockIdx.z * chunksPerSplit;
    int c1 = min(totalChunks, c0 + chunksPerSplit);
    if (c0 >= c1) return;

    int r = tid >> 1, q = (tid & 1) * 16;
    const __half* pAh = Ah + (size_t)(m0 + r) * lda + q;
    const __half* pAl = Al + (size_t)(m0 + r) * lda + q;
    const __half* pBh = Bh + (size_t)(n0 + r) * ldb + q;
    const __half* pBl = Bl + (size_t)(n0 + r) * ldb + q;
    __half* sAh_w = sAh + r * ASTR + q;
    __half* sAl_w = sAl + r * ASTR + q;
    __half* sBh_w = sBh + r * ASTR + q;
    __half* sBl_w = sBl + r * ASTR + q;

    uint32_t bAh = smem_u32(sAh), bAl = smem_u32(sAl);
    uint32_t bBh = smem_u32(sBh), bBl = smem_u32(sBl);
    int lrow = lane & 15, lcol = (lane >> 4) * 8;
    uint32_t ofsA[2], ofsB[4];
#pragma unroll
    for (int mt = 0; mt < 2; mt++)
        ofsA[mt] = ((mw * 32 + mt * 16 + lrow) * ASTR + lcol) * 2;
#pragma unroll
    for (int ng = 0; ng < 4; ng++)
        ofsB[ng] = ((nw * 64 + ng * 16 + lrow) * ASTR + lcol) * 2;

    float acc[2][8][4] = {};

    for (int c = c0; c < c1; c++) {
        size_t k0 = (size_t)c * 32;
        float4 v0, v1;
        v0 = *(const float4*)(pAh + k0); v1 = *(const float4*)(pAh + k0 + 8);
        *(float4*)sAh_w = v0; *(float4*)(sAh_w + 8) = v1;
        v0 = *(const float4*)(pAl + k0); v1 = *(const float4*)(pAl + k0 + 8);
        *(float4*)sAl_w = v0; *(float4*)(sAl_w + 8) = v1;
        v0 = *(const float4*)(pBh + k0); v1 = *(const float4*)(pBh + k0 + 8);
        *(float4*)sBh_w = v0; *(float4*)(sBh_w + 8) = v1;
        v0 = *(const float4*)(pBl + k0); v1 = *(const float4*)(pBl + k0 + 8);
        *(float4*)sBl_w = v0; *(float4*)(sBl_w + 8) = v1;
        __syncthreads();

#pragma unroll
        for (int ks = 0; ks < 2; ks++) {
            uint32_t ah[2][4], al[2][4];
            ldm4(ah[0], bAh + ofsA[0] + ks * 32);
            ldm4(ah[1], bAh + ofsA[1] + ks * 32);
            ldm4(al[0], bAl + ofsA[0] + ks * 32);
            ldm4(al[1], bAl + ofsA[1] + ks * 32);
#pragma unroll
            for (int ng = 0; ng < 4; ng++) {
                uint32_t bh[4], bl[4];
                ldm4(bh, bBh + ofsB[ng] + ks * 32);
                ldm4(bl, bBl + ofsB[ng] + ks * 32);
#pragma unroll
                for (int mt = 0; mt < 2; mt++) {
                    float* d0 = acc[mt][2 * ng];
                    float* d1 = acc[mt][2 * ng + 1];
                    mma16816(d0, ah[mt], bh[0], bh[2]);
                    mma16816(d0, ah[mt], bl[0], bl[2]);
                    mma16816(d0, al[mt], bh[0], bh[2]);
                    mma16816(d1, ah[mt], bh[1], bh[3]);
                    mma16816(d1, ah[mt], bl[1], bl[3]);
                    mma16816(d1, al[mt], bh[1], bh[3]);
                }
            }
        }
        __syncthreads();
    }

    int gid = lane >> 2, tig = lane & 3;
#pragma unroll
    for (int mt = 0; mt < 2; mt++) {
        int row = m0 + mw * 32 + mt * 16 + gid;
#pragma unroll
        for (int nt = 0; nt < 8; nt++) {
            int col = n0 + nw * 64 + nt * 8 + tig * 2;
            float* p0 = Cacc + (size_t)row * ldc + col;
            float* p1 = Cacc + (size_t)(row + 8) * ldc + col;
            atomicAdd(p0,     acc[mt][nt][0]);
            atomicAdd(p0 + 1, acc[mt][nt][1]);
            atomicAdd(p1,     acc[mt][nt][2]);
            atomicAdd(p1 + 1, acc[mt][nt][3]);
        }
    }
}

// =============== fused conv + fc1_xt GEMM (A computed in-smem) ===============
// K reordered: k = tpos*32 + f. Chunk c == tpos c, covering all 32 filters.
// Dynamic smem layout (bytes):
#define CG_LUT   0
#define CG_BIAS  (CG_LUT + KW * NFLT * VOCAB * 4)          // 26624
#define CG_TOK   (CG_BIAS + 128)                            // 26752
#define CG_AH    (CG_TOK + 128 * TOKSLAB * 4)               // 44160
#define CG_AL    (CG_AH + 128 * ASTR * 2)                   // 54400
#define CG_BH    (CG_AL + 128 * ASTR * 2)                   // 64640
#define CG_BL    (CG_BH + 128 * ASTR * 2)                   // 74880
#define CG_TOTAL (CG_BL + 128 * ASTR * 2)                   // 85120

__global__ void __launch_bounds__(256, 2) cgemm(
    const int* __restrict__ target, const float* __restrict__ convbias,
    const __half* __restrict__ Bh, const __half* __restrict__ Bl,
    float* __restrict__ Cacc)
{
    extern __shared__ char dsm[];
    float* lut_s  = (float*)(dsm + CG_LUT);
    float* bias_s = (float*)(dsm + CG_BIAS);
    int*   tok_s  = (int*)(dsm + CG_TOK);
    __half* sAh = (__half*)(dsm + CG_AH);
    __half* sAl = (__half*)(dsm + CG_AL);
    __half* sBh = (__half*)(dsm + CG_BH);
    __half* sBl = (__half*)(dsm + CG_BL);

    int tid = threadIdx.x, lane = tid & 31, wid = tid >> 5;
    int mw = wid & 3, nw = wid >> 2;
    int m0 = blockIdx.y * 128;

    int c0 = blockIdx.z * CPS_XT;
    int c1 = min(CONVL, c0 + CPS_XT);
    if (c0 >= c1) return;

    // stage LUT, bias, tokens
    for (int i = tid; i < KW * NFLT * VOCAB; i += 256) lut_s[i] = g_lut[i];
    if (tid < NFLT) bias_s[tid] = convbias[tid];
    for (int i = tid; i < 128 * TOKSLAB; i += 256) {
        int row = i / TOKSLAB, j = i - row * TOKSLAB;
        int tp = c0 + j;
        tok_s[i] = (tp < SEQ) ? target[(size_t)(m0 + row) * SEQ + tp] : 0;
    }

    int r = tid >> 1, q = (tid & 1) * 16;
    const __half* pBh = Bh + (size_t)r * FLAT + q;
    const __half* pBl = Bl + (size_t)r * FLAT + q;
    __half* sAh_w = sAh + r * ASTR + q;
    __half* sAl_w = sAl + r * ASTR + q;
    __half* sBh_w = sBh + r * ASTR + q;
    __half* sBl_w = sBl + r * ASTR + q;

    uint32_t bAh = smem_u32(sAh), bAl = smem_u32(sAl);
    uint32_t bBh = smem_u32(sBh), bBl = smem_u32(sBl);
    int lrow = lane & 15, lcol = (lane >> 4) * 8;
    uint32_t ofsA[2], ofsB[4];
#pragma unroll
    for (int mt = 0; mt < 2; mt++)
        ofsA[mt] = ((mw * 32 + mt * 16 + lrow) * ASTR + lcol) * 2;
#pragma unroll
    for (int ng = 0; ng < 4; ng++)
        ofsB[ng] = ((nw * 64 + ng * 16 + lrow) * ASTR + lcol) * 2;

    float acc[2][8][4] = {};
    __syncthreads();   // staging done

    for (int c = c0; c < c1; c++) {
        // ---- compute A tile: row r, filters q..q+15, tpos c ----
        int cc = c - c0;
        int tk[KW];
#pragma unroll
        for (int k = 0; k < KW; k++) tk[k] = tok_s[r * TOKSLAB + cc + k];
        __half2 hb[8], lb[8];
#pragma unroll
        for (int fi = 0; fi < 16; fi += 2) {
            float v[2];
#pragma unroll
            for (int u = 0; u < 2; u++) {
                int f = q + fi + u;
                float a = bias_s[f];
#pragma unroll
                for (int k = 0; k < KW; k++)
                    a += lut_s[(k * NFLT + f) * VOCAB + tk[k]];
                v[u] = fmaxf(a, 0.f);
            }
            __half h0, l0, h1, l1;
            split16(v[0], h0, l0); split16(v[1], h1, l1);
            hb[fi >> 1] = __halves2half2(h0, h1);
            lb[fi >> 1] = __halves2half2(l0, l1);
        }
        *(float4*)sAh_w = *(float4*)&hb[0];
        *(float4*)(sAh_w + 8) = *(float4*)&hb[4];
        *(float4*)sAl_w = *(float4*)&lb[0];
        *(float4*)(sAl_w + 8) = *(float4*)&lb[4];

        // ---- B tile from gmem ----
        size_t k0 = (size_t)c * 32;
        float4 v0, v1;
        v0 = *(const float4*)(pBh + k0); v1 = *(const float4*)(pBh + k0 + 8);
        *(float4*)sBh_w = v0; *(float4*)(sBh_w + 8) = v1;
        v0 = *(const float4*)(pBl + k0); v1 = *(const float4*)(pBl + k0 + 8);
        *(float4*)sBl_w = v0; *(float4*)(sBl_w + 8) = v1;
        __syncthreads();

#pragma unroll
        for (int ks = 0; ks < 2; ks++) {
            uint32_t ah[2][4], al[2][4];
            ldm4(ah[0], bAh + ofsA[0] + ks * 32);
            ldm4(ah[1], bAh + ofsA[1] + ks * 32);
            ldm4(al[0], bAl + ofsA[0] + ks * 32);
            ldm4(al[1], bAl + ofsA[1] + ks * 32);
#pragma unroll
            for (int ng = 0; ng < 4; ng++) {
                uint32_t bh[4], bl[4];
                ldm4(bh, bBh + ofsB[ng] + ks * 32);
                ldm4(bl, bBl + ofsB[ng] + ks * 32);
#pragma unroll
                for (int mt = 0; mt < 2; mt++) {
                    float* d0 = acc[mt][2 * ng];
                    float* d1 = acc[mt][2 * ng + 1];
                    mma16816(d0, ah[mt], bh[0], bh[2]);
                    mma16816(d0, ah[mt], bl[0], bl[2]);
                    mma16816(d0, al[mt], bh[0], bh[2]);
                    mma16816(d1, ah[mt], bh[1], bh[3]);
                    mma16816(d1, ah[mt], bl[1], bl[3]);
                    mma16816(d1, al[mt], bh[1], bh[3]);
                }
            }
        }
        __syncthreads();
    }

    int gid = lane >> 2, tig = lane & 3;
#pragma unroll
    for (int mt = 0; mt < 2; mt++) {
        int row = m0 + mw * 32 + mt * 16 + gid;
#pragma unroll
        for (int nt = 0; nt < 8; nt++) {
            int col = nw * 64 + nt * 8 + tig * 2;
            float* p0 = Cacc + (size_t)row * OUTD + col;
            float* p1 = Cacc + (size_t)(row + 8) * OUTD + col;
            atomicAdd(p0,     acc[mt][nt][0]);
            atomicAdd(p0 + 1, acc[mt][nt][1]);
            atomicAdd(p1,     acc[mt][nt][2]);
            atomicAdd(p1 + 1, acc[mt][nt][3]);
        }
    }
}

// -------------------------- GIN: projection p = bn(h) @ Wa ------------------
template <int FIN, bool HASBN>
__global__ void __launch_bounds__(256) proj_kernel(
    const float* __restrict__ hin, const float* __restrict__ wa,
    float* __restrict__ p)
{
    __shared__ float wa_s[FIN * DIM];
    __shared__ float bsc[DIM], bsh[DIM];
    int tid = threadIdx.x;
    for (int i = tid; i < FIN * DIM; i += blockDim.x) wa_s[i] = wa[i];
    if (HASBN && tid < DIM) { bsc[tid] = g_bn[tid]; bsh[tid] = g_bn[DIM + tid]; }
    __syncthreads();

    int lane = tid & 31;
    int node = blockIdx.x * (blockDim.x >> 5) + (tid >> 5);
    if (node >= N_ATOMS) return;

    const float* row = hin + (size_t)node * FIN;
    float acc = 0.f;
#pragma unroll 4
    for (int c = 0; c < FIN; c++) {
        float v = __ldg(row + c);
        if (HASBN) v = fmaf(v, bsc[c], bsh[c]);
        acc = fmaf(v, wa_s[c * DIM + lane], acc);
    }
    p[node * DIM + lane] = acc;
}

// ---- GIN fused: gather (CSR) + y = relu(relu(t+ba)@Wb + bb) + BN stats -----
__global__ void __launch_bounds__(256) mlp2agg_kernel(
    const float* __restrict__ p, const float* __restrict__ wb,
    const float* __restrict__ ba, const float* __restrict__ bb,
    float* __restrict__ y, float* __restrict__ stats)
{
    __shared__ float wb_s[DIM * DIM];
    int tid = threadIdx.x;
    for (int i = tid; i < DIM * DIM; i += blockDim.x) wb_s[i] = wb[i];
    __syncthreads();

    int lane = tid & 31;
    int warpId = blockIdx.x * (blockDim.x >> 5) + (tid >> 5);
    int nWarps = gridDim.x * (blockDim.x >> 5);
    float bav = ba[lane], bbv = bb[lane];
    float s0 = 0.f, s1 = 0.f;

    for (int i = warpId; i < N_ATOMS; i += nWarps) {
        int rr = (lane < 2) ? g_rowptr[i + lane] : 0;
        int r0 = __shfl_sync(0xffffffffu, rr, 0);
        int r1 = __shfl_sync(0xffffffffu, rr, 1);

        float t = p[(size_t)i * DIM + lane];
        for (int base = r0; base < r1; base += 32) {
            int myE = base + lane;
            int s = (myE < r1) ? g_esorted[myE] : 0;
            int cnt = min(r1 - base, 32);
            for (int j = 0; j < cnt; j++) {
                int sj = __shfl_sync(0xffffffffu, s, j);
                t += p[(size_t)sj * DIM + lane];
            }
        }

        float hidden = fmaxf(t + bav, 0.f);
        float acc = bbv;
#pragma unroll
        for (int c = 0; c < DIM; c++) {
            float hv = __shfl_sync(0xffffffffu, hidden, c);
            acc = fmaf(hv, wb_s[c * DIM + lane], acc);
        }
        float yv = fmaxf(acc, 0.f);
        y[(size_t)i * DIM + lane] = yv;
        s0 += yv;
        s1 += yv * yv;
    }
    atomicAdd(&stats[lane], s0);
    atomicAdd(&stats[DIM + lane], s1);
}

// --------------------------- GIN: BN finalize -------------------------------
__global__ void bnfin_kernel(const float* __restrict__ stats,
                             const float* __restrict__ gamma,
                             const float* __restrict__ beta)
{
    int c = threadIdx.x;
    float mu = stats[c] * (1.0f / N_ATOMS);
    float var = stats[DIM + c] * (1.0f / N_ATOMS) - mu * mu;
    float sc = gamma[c] * rsqrtf(var + 1e-5f);
    g_bn[c] = sc;
    g_bn[DIM + c] = beta[c] - mu * sc;
}

// ------------------- global add pool: segmented (batch sorted) --------------
__global__ void pool2_kernel(const float* __restrict__ y, const int* __restrict__ batch,
                             float* __restrict__ xg)
{
    int lane = threadIdx.x & 31;
    int warp = (blockIdx.x * blockDim.x + threadIdx.x) >> 5;
    int nb = warp * 32;
    if (nb >= N_ATOMS) return;
    float sc = g_bn[lane], sh = g_bn[DIM + lane];

    int bt = (nb + lane < N_ATOMS) ? batch[nb + lane] : -1;
    int cur = __shfl_sync(0xffffffffu, bt, 0);
    float sum = 0.f;
    int last = min(32, N_ATOMS - nb);
    for (int j = 0; j < last; j++) {
        int b = __shfl_sync(0xffffffffu, bt, j);
        float v = fmaf(y[(size_t)(nb + j) * DIM + lane], sc, sh);
        if (b != cur) {
            atomicAdd(&xg[cur * DIM + lane], sum);
            sum = 0.f; cur = b;
        }
        sum += v;
    }
    atomicAdd(&xg[cur * DIM + lane], sum);
}

// -------- build xc: fc1_xd (cols 0..127) + LM copy (cols 256..2303) ---------
__global__ void xcfill_kernel(const float* __restrict__ xg, const float* __restrict__ w,
                              const float* __restrict__ bias,
                              const float* __restrict__ drug, const float* __restrict__ prot)
{
    int idx = blockIdx.x * blockDim.x + threadIdx.x;
    int total = BGR * (OUTD + 2 * LMDIM);
    if (idx >= total) return;
    int b = idx / (OUTD + 2 * LMDIM);
    int j = idx - b * (OUTD + 2 * LMDIM);
    float v;
    size_t d;
    if (j < OUTD) {
        float acc = bias[j];
#pragma unroll
        for (int c = 0; c < DIM; c++) acc = fmaf(xg[b * DIM + c], w[c * OUTD + j], acc);
        v = fmaxf(acc, 0.f);
        d = (size_t)b * COMB + j;
    } else {
        int jj = j - OUTD;
        v = (jj < LMDIM) ? drug[b * LMDIM + jj] : prot[b * LMDIM + (jj - LMDIM)];
        d = (size_t)b * COMB + 2 * OUTD + jj;
    }
    __half h, l; split16(v, h, l);
    g_XCh[d] = h; g_XCl[d] = l;
}

// ------------------------- conv LUT: M[k][f][v] ------------------------------
__global__ void lut_kernel(const float* __restrict__ emb, const float* __restrict__ w)
{
    int idx = blockIdx.x * blockDim.x + threadIdx.x;
    if (idx >= KW * NFLT * VOCAB) return;
    int v = idx % VOCAB;
    int f = (idx / VOCAB) % NFLT;
    int k = idx / (VOCAB * NFLT);
    float acc = 0.f;
#pragma unroll 4
    for (int c = 0; c < EMBD; c++)
        acc = fmaf(emb[v * EMBD + c], w[f * EMBD * KW + c * KW + k], acc);
    g_lut[idx] = acc;
}

// ------------- split-K epilogue: relu(acc+bias) -> fp16 hi/lo pair ----------
__global__ void epi16_kernel(const float* __restrict__ acc, const float* __restrict__ bias,
                             __half* __restrict__ Xh, __half* __restrict__ Xl,
                             int rows, int cols, int dstStride, int dstOff)
{
    int idx = blockIdx.x * blockDim.x + threadIdx.x;
    if (idx >= rows * cols) return;
    int r = idx / cols, c = idx - r * cols;
    float v = fmaxf(acc[idx] + bias[c], 0.f);
    __half h, l; split16(v, h, l);
    size_t d = (size_t)r * dstStride + dstOff + c;
    Xh[d] = h; Xl[d] = l;
}

// ---------------------- fp32 epilogue (h2) ----------------------------------
__global__ void epi_kernel(const float* __restrict__ acc, const float* __restrict__ bias,
                           float* __restrict__ dst, int rows, int cols)
{
    int idx = blockIdx.x * blockDim.x + threadIdx.x;
    if (idx >= rows * cols) return;
    int c = idx % cols;
    dst[idx] = fmaxf(acc[idx] + bias[c], 0.f);
}

// --------------------------- final output layer -----------------------------
__global__ void out_kernel(const float* __restrict__ h2, const float* __restrict__ w,
                           const float* __restrict__ b, float* __restrict__ out)
{
    int tid = threadIdx.x;
    int lane = tid & 31;
    int row = blockIdx.x * (blockDim.x >> 5) + (tid >> 5);
    if (row >= BGR) return;
    float acc = 0.f;
#pragma unroll
    for (int k = 0; k < H2DIM / 32; k++)
        acc = fmaf(h2[row * H2DIM + k * 32 + lane], w[k * 32 + lane], acc);
#pragma unroll
    for (int off = 16; off; off >>= 1) acc += __shfl_xor_sync(0xffffffffu, acc, off);
    if (lane == 0) out[row] = acc + b[0];
}

// ================================ launcher ===================================
extern "C" void kernel_launch(void* const* d_in, const int* in_sizes, int n_in,
                              void* d_out, int out_size)
{
    (void)in_sizes; (void)n_in; (void)out_size;
    const float* x        = (const float*)d_in[0];
    const int*   ei       = (const int*)d_in[1];
    const int*   batch    = (const int*)d_in[2];
    const int*   target   = (const int*)d_in[3];
    const float* drug_lm  = (const float*)d_in[4];
    const float* prot_lm  = (const float*)d_in[5];
    const float* w1a      = (const float*)d_in[6];
    const float* b1a      = (const float*)d_in[7];
    const float* w1b      = (const float*)d_in[8];
    const float* b1b      = (const float*)d_in[9];
    const float* gw_a     = (const float*)d_in[10];
    const float* gb_a     = (const float*)d_in[11];
    const float* gw_b     = (const float*)d_in[12];
    const float* gb_b     = (const float*)d_in[13];
    const float* bn_gamma = (const float*)d_in[14];
    const float* bn_beta  = (const float*)d_in[15];
    const float* fc1_xd_w = (const float*)d_in[16];
    const float* fc1_xd_b = (const float*)d_in[17];
    const float* emb      = (const float*)d_in[18];
    const float* convxt_w = (const float*)d_in[19];
    const float* convxt_b = (const float*)d_in[20];
    const float* fc1_xt_w = (const float*)d_in[21];
    const float* fc1_xt_b = (const float*)d_in[22];
    const float* fc1_w    = (const float*)d_in[23];
    const float* fc1_b    = (const float*)d_in[24];
    const float* fc2_w    = (const float*)d_in[25];
    const float* fc2_b    = (const float*)d_in[26];
    const float* out_w    = (const float*)d_in[27];
    const float* out_b    = (const float*)d_in[28];
    float* out = (float*)d_out;

    const int* srcp = ei;
    const int* dstp = ei + EDGES;

    void* vp;
    cudaGetSymbolAddress(&vp, g_p);      float* p_p     = (float*)vp;
    cudaGetSymbolAddress(&vp, g_y);      float* p_y     = (float*)vp;
    cudaGetSymbolAddress(&vp, g_stats);  float* p_stats = (float*)vp;
    cudaGetSymbolAddress(&vp, g_xg);     float* p_xg    = (float*)vp;
    cudaGetSymbolAddress(&vp, g_BxtH);   __half* p_BxtH = (__half*)vp;
    cudaGetSymbolAddress(&vp, g_BxtL);   __half* p_BxtL = (__half*)vp;
    cudaGetSymbolAddress(&vp, g_B1H);    __half* p_B1H  = (__half*)vp;
    cudaGetSymbolAddress(&vp, g_B1L);    __half* p_B1L  = (__half*)vp;
    cudaGetSymbolAddress(&vp, g_B2H);    __half* p_B2H  = (__half*)vp;
    cudaGetSymbolAddress(&vp, g_B2L);    __half* p_B2L  = (__half*)vp;
    cudaGetSymbolAddress(&vp, g_XCh);    __half* p_XCh  = (__half*)vp;
    cudaGetSymbolAddress(&vp, g_XCl);    __half* p_XCl  = (__half*)vp;
    cudaGetSymbolAddress(&vp, g_H1h);    __half* p_H1h  = (__half*)vp;
    cudaGetSymbolAddress(&vp, g_H1l);    __half* p_H1l  = (__half*)vp;
    cudaGetSymbolAddress(&vp, g_xtacc);  float* p_xtacc = (float*)vp;
    cudaGetSymbolAddress(&vp, g_h1acc);  float* p_h1acc = (float*)vp;
    cudaGetSymbolAddress(&vp, g_h2acc);  float* p_h2acc = (float*)vp;
    cudaGetSymbolAddress(&vp, g_h2);     float* p_h2    = (float*)vp;

    cudaFuncSetAttribute(cgemm, cudaFuncAttributeMaxDynamicSharedMemorySize, CG_TOTAL);

    // 0) zero accumulators + CSR build + weight conversions + LUT
    zero_kernel<<<512, 256>>>();
    hist_kernel<<<(EDGES + 255) / 256, 256>>>(dstp);
    scan1_kernel<<<NB_SCAN, 256>>>();
    scan2_kernel<<<1, 512>>>();
    scan3_kernel<<<NB_SCAN, 256>>>();
    scatter_kernel<<<(EDGES + 255) / 256, 256>>>(srcp, dstp);

    { dim3 g(CONVL, OUTD / 32);      w16tx_kernel<<<g, 256>>>(fc1_xt_w, p_BxtH, p_BxtL); }
    { dim3 g(COMB / 32, H1DIM / 32); w16t_kernel<<<g, 256>>>(fc1_w, p_B1H, p_B1L, COMB, H1DIM); }
    { dim3 g(H1DIM / 32, H2DIM / 32); w16t_kernel<<<g, 256>>>(fc2_w, p_B2H, p_B2L, H1DIM, H2DIM); }
    lut_kernel<<<(KW * NFLT * VOCAB + 255) / 256, 256>>>(emb, convxt_w);

    // 1) protein branch: fused conv+GEMM (split-K 37)
    {
        dim3 grid(1, BGR / 128, SPLITS_XT);   // 296 CTAs = one wave @2/SM
        cgemm<<<grid, 256, CG_TOTAL>>>(target, convxt_b, p_BxtH, p_BxtL, p_xtacc);
    }
    epi16_kernel<<<(BGR * OUTD + 255) / 256, 256>>>(p_xtacc, fc1_xt_b, p_XCh, p_XCl,
                                                    BGR, OUTD, COMB, OUTD);

    // 2) GIN layers (CSR gather, no atomics)
    for (int l = 0; l < 5; l++) {
        const float* wa = (l == 0) ? w1a : gw_a + (l - 1) * DIM * DIM;
        const float* ba = (l == 0) ? b1a : gb_a + (l - 1) * DIM;
        const float* wb = (l == 0) ? w1b : gw_b + (l - 1) * DIM * DIM;
        const float* bb = (l == 0) ? b1b : gb_b + (l - 1) * DIM;
        if (l == 0)
            proj_kernel<FXD, false><<<(N_ATOMS + 7) / 8, 256>>>(x, wa, p_p);
        else
            proj_kernel<DIM, true><<<(N_ATOMS + 7) / 8, 256>>>(p_y, wa, p_p);
        mlp2agg_kernel<<<512, 256>>>(p_p, wb, ba, bb, p_y, p_stats + l * 2 * DIM);
        bnfin_kernel<<<1, DIM>>>(p_stats + l * 2 * DIM, bn_gamma + l * DIM, bn_beta + l * DIM);
    }

    // 3) pool (segmented) + xc fill
    pool2_kernel<<<(N_ATOMS / 32 + 7) / 8, 256>>>(p_y, batch, p_xg);
    xcfill_kernel<<<(BGR * (OUTD + 2 * LMDIM) + 255) / 256, 256>>>(
        p_xg, fc1_xd_w, fc1_xd_b, drug_lm, prot_lm);

    // 4) head MLP: fc1 (split-K 4), fc2 (split-K 16), out
    {
        dim3 grid(H1DIM / 128, BGR / 128, 4);   // 256 CTAs, one wave
        hgemm<<<grid, 256>>>(p_XCh, p_XCl, p_B1H, p_B1L, p_h1acc,
                             COMB, COMB, H1DIM, COMB / 32, 18);
    }
    epi16_kernel<<<(BGR * H1DIM + 255) / 256, 256>>>(p_h1acc, fc1_b, p_H1h, p_H1l,
                                                     BGR, H1DIM, H1DIM, 0);
    {
        dim3 grid(H2DIM / 128, BGR / 128, 16);  // 256 CTAs, one wave
        hgemm<<<grid, 256>>>(p_H1h, p_H1l, p_B2H, p_B2L, p_h2acc,
                             H1DIM, H1DIM, H2DIM, H1DIM / 32, 2);
    }
    epi_kernel<<<(BGR * H2DIM + 255) / 256, 256>>>(p_h2acc, fc2_b, p_h2, BGR, H2DIM);
    out_kernel<<<BGR / 8, 256>>>(p_h2, out_w, out_b, out);
}

// round 6
// speedup vs baseline: 1.1358x; 1.1358x over previous
#include <cuda_runtime.h>
#include <cuda_fp16.h>
#include <cstdint>

#define N_ATOMS 100000
#define EDGES   400000
#define BGR     1024
#define FXD     78
#define DIM     32
#define OUTD    128
#define EMBD    128
#define VOCAB   26
#define NFLT    32
#define SEQ     1000
#define KW      8
#define CONVL   993           // SEQ - KW + 1
#define FLAT    31776         // NFLT * CONVL
#define COMB    2304          // 2*OUTD + 2*1024
#define H1DIM   1024
#define H2DIM   256
#define LMDIM   1024
#define NB_SCAN ((N_ATOMS + 255) / 256)   // 391

#define SPLITS_XT 37
#define CPS_XT    27          // 37*27 = 999 >= 993 chunks (1 chunk = 1 tpos)
#define TOKSLAB   (CPS_XT + 7)  // 34 tokens per protein per split

// ------------------------- scratch (device globals) -------------------------
__device__ float g_p[N_ATOMS * DIM];
__device__ float g_y[N_ATOMS * DIM];
__device__ float g_y2[N_ATOMS * DIM];
__device__ float g_stats[5 * 2 * DIM];
__device__ float g_xg[BGR * DIM];
__device__ float g_lut[KW * NFLT * VOCAB];

// CSR scratch
__device__ int g_deg[N_ATOMS];
__device__ int g_rowptr[N_ATOMS + 1];
__device__ int g_cur[N_ATOMS];
__device__ int g_esorted[EDGES];
__device__ int g_blocksum[512];

// fp16 hi/lo weight & activation buffers
__device__ __half g_BxtH[(size_t)OUTD * FLAT];   // fc1_xt_w reordered+T
__device__ __half g_BxtL[(size_t)OUTD * FLAT];
__device__ __half g_B1H[(size_t)H1DIM * COMB];   // fc1_w^T
__device__ __half g_B1L[(size_t)H1DIM * COMB];
__device__ __half g_B2H[(size_t)H2DIM * H1DIM];  // fc2_w^T
__device__ __half g_B2L[(size_t)H2DIM * H1DIM];
__device__ __half g_XCh[(size_t)BGR * COMB];
__device__ __half g_XCl[(size_t)BGR * COMB];
__device__ __half g_H1h[(size_t)BGR * H1DIM];
__device__ __half g_H1l[(size_t)BGR * H1DIM];

__device__ float g_xtacc[BGR * OUTD];
__device__ float g_h1acc[BGR * H1DIM];
__device__ float g_h2acc[BGR * H2DIM];
__device__ float g_h2[BGR * H2DIM];

__device__ __forceinline__ void split16(float v, __half& h, __half& l) {
    h = __float2half_rn(v);
    l = __float2half_rn(v - __half2float(h));
}

// ------------------------------- zero scratch -------------------------------
__global__ void zero_kernel() {
    int idx = blockIdx.x * blockDim.x + threadIdx.x;
    int stride = gridDim.x * blockDim.x;
    for (int i = idx; i < BGR * OUTD; i += stride) g_xtacc[i] = 0.f;
    for (int i = idx; i < BGR * H1DIM; i += stride) g_h1acc[i] = 0.f;
    for (int i = idx; i < BGR * H2DIM; i += stride) g_h2acc[i] = 0.f;
    for (int i = idx; i < BGR * DIM; i += stride) g_xg[i] = 0.f;
    for (int i = idx; i < 5 * 2 * DIM; i += stride) g_stats[i] = 0.f;
    for (int i = idx; i < N_ATOMS; i += stride) g_deg[i] = 0;
}

// ----------------------------- CSR construction -----------------------------
__global__ void hist_kernel(const int* __restrict__ dst) {
    int e = blockIdx.x * blockDim.x + threadIdx.x;
    if (e < EDGES) atomicAdd(&g_deg[dst[e]], 1);
}

__global__ void scan1_kernel() {
    __shared__ int s[256];
    int tid = threadIdx.x;
    int i = blockIdx.x * 256 + tid;
    int v = (i < N_ATOMS) ? g_deg[i] : 0;
    s[tid] = v;
    __syncthreads();
#pragma unroll
    for (int o = 1; o < 256; o <<= 1) {
        int u = (tid >= o) ? s[tid - o] : 0;
        __syncthreads();
        s[tid] += u;
        __syncthreads();
    }
    if (i < N_ATOMS) g_rowptr[i] = s[tid] - v;
    if (tid == 255) g_blocksum[blockIdx.x] = s[255];
}

__global__ void scan2_kernel() {
    __shared__ int s[512];
    int tid = threadIdx.x;
    int v = (tid < NB_SCAN) ? g_blocksum[tid] : 0;
    s[tid] = v;
    __syncthreads();
#pragma unroll
    for (int o = 1; o < 512; o <<= 1) {
        int u = (tid >= o) ? s[tid - o] : 0;
        __syncthreads();
        s[tid] += u;
        __syncthreads();
    }
    if (tid < NB_SCAN) g_blocksum[tid] = s[tid] - v;
}

__global__ void scan3_kernel() {
    int i = blockIdx.x * blockDim.x + threadIdx.x;
    if (i < N_ATOMS) {
        int v = g_rowptr[i] + g_blocksum[i >> 8];
        g_rowptr[i] = v;
        g_cur[i] = v;
    }
    if (i == 0) g_rowptr[N_ATOMS] = EDGES;
}

__global__ void scatter_kernel(const int* __restrict__ src, const int* __restrict__ dst) {
    int e = blockIdx.x * blockDim.x + threadIdx.x;
    if (e >= EDGES) return;
    int pos = atomicAdd(&g_cur[dst[e]], 1);
    g_esorted[pos] = src[e];
}

// -------------- weight transpose + fp16 split: W[K][N] -> Bt[N][K] ----------
__global__ void w16t_kernel(const float* __restrict__ W,
                            __half* __restrict__ Bh, __half* __restrict__ Bl,
                            int K, int N)
{
    __shared__ float ts[32][33];
    int k0 = blockIdx.x * 32, n0 = blockIdx.y * 32;
    int tx = threadIdx.x & 31, ty = threadIdx.x >> 5;
#pragma unroll
    for (int i = 0; i < 4; i++)
        ts[ty + i * 8][tx] = W[(size_t)(k0 + ty + i * 8) * N + n0 + tx];
    __syncthreads();
#pragma unroll
    for (int i = 0; i < 4; i++) {
        int n = ty + i * 8;
        float v = ts[tx][n];
        __half h, l; split16(v, h, l);
        size_t o = (size_t)(n0 + n) * K + k0 + tx;
        Bh[o] = h; Bl[o] = l;
    }
}

// ------ fc1_xt weight: reorder K (f*993+t -> t*32+f), transpose, split ------
__global__ void w16tx_kernel(const float* __restrict__ W,
                             __half* __restrict__ Bh, __half* __restrict__ Bl)
{
    __shared__ float ts[32][33];
    int t = blockIdx.x;
    int n0 = blockIdx.y * 32;
    int tx = threadIdx.x & 31, ty = threadIdx.x >> 5;
#pragma unroll
    for (int i = 0; i < 4; i++) {
        int f = ty + i * 8;
        ts[f][tx] = W[(size_t)(f * CONVL + t) * OUTD + n0 + tx];
    }
    __syncthreads();
#pragma unroll
    for (int i = 0; i < 4; i++) {
        int n = ty + i * 8;
        float v = ts[tx][n];
        __half h, l; split16(v, h, l);
        size_t o = (size_t)(n0 + n) * FLAT + t * 32 + tx;
        Bh[o] = h; Bl[o] = l;
    }
}

// =========================== fp16x3 MMA helpers ==============================
#define ASTR 40

__device__ __forceinline__ uint32_t smem_u32(const void* p) {
    uint32_t a;
    asm("{ .reg .u64 t; cvta.to.shared.u64 t, %1; cvt.u32.u64 %0, t; }"
        : "=r"(a) : "l"(p));
    return a;
}
__device__ __forceinline__ void ldm4(uint32_t* r, uint32_t saddr) {
    asm volatile("ldmatrix.sync.aligned.m8n8.x4.shared.b16 {%0,%1,%2,%3}, [%4];"
        : "=r"(r[0]), "=r"(r[1]), "=r"(r[2]), "=r"(r[3]) : "r"(saddr));
}
__device__ __forceinline__ void mma16816(float* d, const uint32_t* a,
                                         uint32_t b0, uint32_t b1) {
    asm volatile(
        "mma.sync.aligned.m16n8k16.row.col.f32.f16.f16.f32 "
        "{%0,%1,%2,%3}, {%4,%5,%6,%7}, {%8,%9}, {%0,%1,%2,%3};"
        : "+f"(d[0]), "+f"(d[1]), "+f"(d[2]), "+f"(d[3])
        : "r"(a[0]), "r"(a[1]), "r"(a[2]), "r"(a[3]), "r"(b0), "r"(b1));
}

// ============================ generic hgemm ==================================
__global__ void __launch_bounds__(256, 2) hgemm(
    const __half* __restrict__ Ah, const __half* __restrict__ Al,
    const __half* __restrict__ Bh, const __half* __restrict__ Bl,
    float* __restrict__ Cacc, int lda, int ldb, int ldc,
    int totalChunks, int chunksPerSplit)
{
    __shared__ __half sAh[128 * ASTR], sAl[128 * ASTR];
    __shared__ __half sBh[128 * ASTR], sBl[128 * ASTR];

    int tid = threadIdx.x, lane = tid & 31, wid = tid >> 5;
    int mw = wid & 3, nw = wid >> 2;
    int m0 = blockIdx.y * 128, n0 = blockIdx.x * 128;

    int c0 = blockIdx.z * chunksPerSplit;
    int c1 = min(totalChunks, c0 + chunksPerSplit);
    if (c0 >= c1) return;

    int r = tid >> 1, q = (tid & 1) * 16;
    const __half* pAh = Ah + (size_t)(m0 + r) * lda + q;
    const __half* pAl = Al + (size_t)(m0 + r) * lda + q;
    const __half* pBh = Bh + (size_t)(n0 + r) * ldb + q;
    const __half* pBl = Bl + (size_t)(n0 + r) * ldb + q;
    __half* sAh_w = sAh + r * ASTR + q;
    __half* sAl_w = sAl + r * ASTR + q;
    __half* sBh_w = sBh + r * ASTR + q;
    __half* sBl_w = sBl + r * ASTR + q;

    uint32_t bAh = smem_u32(sAh), bAl = smem_u32(sAl);
    uint32_t bBh = smem_u32(sBh), bBl = smem_u32(sBl);
    int lrow = lane & 15, lcol = (lane >> 4) * 8;
    uint32_t ofsA[2], ofsB[4];
#pragma unroll
    for (int mt = 0; mt < 2; mt++)
        ofsA[mt] = ((mw * 32 + mt * 16 + lrow) * ASTR + lcol) * 2;
#pragma unroll
    for (int ng = 0; ng < 4; ng++)
        ofsB[ng] = ((nw * 64 + ng * 16 + lrow) * ASTR + lcol) * 2;

    float acc[2][8][4] = {};

    for (int c = c0; c < c1; c++) {
        size_t k0 = (size_t)c * 32;
        float4 v0, v1;
        v0 = *(const float4*)(pAh + k0); v1 = *(const float4*)(pAh + k0 + 8);
        *(float4*)sAh_w = v0; *(float4*)(sAh_w + 8) = v1;
        v0 = *(const float4*)(pAl + k0); v1 = *(const float4*)(pAl + k0 + 8);
        *(float4*)sAl_w = v0; *(float4*)(sAl_w + 8) = v1;
        v0 = *(const float4*)(pBh + k0); v1 = *(const float4*)(pBh + k0 + 8);
        *(float4*)sBh_w = v0; *(float4*)(sBh_w + 8) = v1;
        v0 = *(const float4*)(pBl + k0); v1 = *(const float4*)(pBl + k0 + 8);
        *(float4*)sBl_w = v0; *(float4*)(sBl_w + 8) = v1;
        __syncthreads();

#pragma unroll
        for (int ks = 0; ks < 2; ks++) {
            uint32_t ah[2][4], al[2][4];
            ldm4(ah[0], bAh + ofsA[0] + ks * 32);
            ldm4(ah[1], bAh + ofsA[1] + ks * 32);
            ldm4(al[0], bAl + ofsA[0] + ks * 32);
            ldm4(al[1], bAl + ofsA[1] + ks * 32);
#pragma unroll
            for (int ng = 0; ng < 4; ng++) {
                uint32_t bh[4], bl[4];
                ldm4(bh, bBh + ofsB[ng] + ks * 32);
                ldm4(bl, bBl + ofsB[ng] + ks * 32);
#pragma unroll
                for (int mt = 0; mt < 2; mt++) {
                    float* d0 = acc[mt][2 * ng];
                    float* d1 = acc[mt][2 * ng + 1];
                    mma16816(d0, ah[mt], bh[0], bh[2]);
                    mma16816(d0, ah[mt], bl[0], bl[2]);
                    mma16816(d0, al[mt], bh[0], bh[2]);
                    mma16816(d1, ah[mt], bh[1], bh[3]);
                    mma16816(d1, ah[mt], bl[1], bl[3]);
                    mma16816(d1, al[mt], bh[1], bh[3]);
                }
            }
        }
        __syncthreads();
    }

    int gid = lane >> 2, tig = lane & 3;
#pragma unroll
    for (int mt = 0; mt < 2; mt++) {
        int row = m0 + mw * 32 + mt * 16 + gid;
#pragma unroll
        for (int nt = 0; nt < 8; nt++) {
            int col = n0 + nw * 64 + nt * 8 + tig * 2;
            float* p0 = Cacc + (size_t)row * ldc + col;
            float* p1 = Cacc + (size_t)(row + 8) * ldc + col;
            atomicAdd(p0,     acc[mt][nt][0]);
            atomicAdd(p0 + 1, acc[mt][nt][1]);
            atomicAdd(p1,     acc[mt][nt][2]);
            atomicAdd(p1 + 1, acc[mt][nt][3]);
        }
    }
}

// =============== fused conv + fc1_xt GEMM (A computed in-smem) ===============
#define CG_LUT   0
#define CG_BIAS  (CG_LUT + KW * NFLT * VOCAB * 4)
#define CG_TOK   (CG_BIAS + 128)
#define CG_AH    (CG_TOK + 128 * TOKSLAB * 4)
#define CG_AL    (CG_AH + 128 * ASTR * 2)
#define CG_BH    (CG_AL + 128 * ASTR * 2)
#define CG_BL    (CG_BH + 128 * ASTR * 2)
#define CG_TOTAL (CG_BL + 128 * ASTR * 2)

__global__ void __launch_bounds__(256, 2) cgemm(
    const int* __restrict__ target, const float* __restrict__ convbias,
    const __half* __restrict__ Bh, const __half* __restrict__ Bl,
    float* __restrict__ Cacc)
{
    extern __shared__ char dsm[];
    float* lut_s  = (float*)(dsm + CG_LUT);
    float* bias_s = (float*)(dsm + CG_BIAS);
    int*   tok_s  = (int*)(dsm + CG_TOK);
    __half* sAh = (__half*)(dsm + CG_AH);
    __half* sAl = (__half*)(dsm + CG_AL);
    __half* sBh = (__half*)(dsm + CG_BH);
    __half* sBl = (__half*)(dsm + CG_BL);

    int tid = threadIdx.x, lane = tid & 31, wid = tid >> 5;
    int mw = wid & 3, nw = wid >> 2;
    int m0 = blockIdx.y * 128;

    int c0 = blockIdx.z * CPS_XT;
    int c1 = min(CONVL, c0 + CPS_XT);
    if (c0 >= c1) return;

    for (int i = tid; i < KW * NFLT * VOCAB; i += 256) lut_s[i] = g_lut[i];
    if (tid < NFLT) bias_s[tid] = convbias[tid];
    for (int i = tid; i < 128 * TOKSLAB; i += 256) {
        int row = i / TOKSLAB, j = i - row * TOKSLAB;
        int tp = c0 + j;
        tok_s[i] = (tp < SEQ) ? target[(size_t)(m0 + row) * SEQ + tp] : 0;
    }

    int r = tid >> 1, q = (tid & 1) * 16;
    const __half* pBh = Bh + (size_t)r * FLAT + q;
    const __half* pBl = Bl + (size_t)r * FLAT + q;
    __half* sAh_w = sAh + r * ASTR + q;
    __half* sAl_w = sAl + r * ASTR + q;
    __half* sBh_w = sBh + r * ASTR + q;
    __half* sBl_w = sBl + r * ASTR + q;

    uint32_t bAh = smem_u32(sAh), bAl = smem_u32(sAl);
    uint32_t bBh = smem_u32(sBh), bBl = smem_u32(sBl);
    int lrow = lane & 15, lcol = (lane >> 4) * 8;
    uint32_t ofsA[2], ofsB[4];
#pragma unroll
    for (int mt = 0; mt < 2; mt++)
        ofsA[mt] = ((mw * 32 + mt * 16 + lrow) * ASTR + lcol) * 2;
#pragma unroll
    for (int ng = 0; ng < 4; ng++)
        ofsB[ng] = ((nw * 64 + ng * 16 + lrow) * ASTR + lcol) * 2;

    float acc[2][8][4] = {};
    __syncthreads();

    for (int c = c0; c < c1; c++) {
        int cc = c - c0;
        int tk[KW];
#pragma unroll
        for (int k = 0; k < KW; k++) tk[k] = tok_s[r * TOKSLAB + cc + k];
        __half2 hb[8], lb[8];
#pragma unroll
        for (int fi = 0; fi < 16; fi += 2) {
            float v[2];
#pragma unroll
            for (int u = 0; u < 2; u++) {
                int f = q + fi + u;
                float a = bias_s[f];
#pragma unroll
                for (int k = 0; k < KW; k++)
                    a += lut_s[(k * NFLT + f) * VOCAB + tk[k]];
                v[u] = fmaxf(a, 0.f);
            }
            __half h0, l0, h1, l1;
            split16(v[0], h0, l0); split16(v[1], h1, l1);
            hb[fi >> 1] = __halves2half2(h0, h1);
            lb[fi >> 1] = __halves2half2(l0, l1);
        }
        *(float4*)sAh_w = *(float4*)&hb[0];
        *(float4*)(sAh_w + 8) = *(float4*)&hb[4];
        *(float4*)sAl_w = *(float4*)&lb[0];
        *(float4*)(sAl_w + 8) = *(float4*)&lb[4];

        size_t k0 = (size_t)c * 32;
        float4 v0, v1;
        v0 = *(const float4*)(pBh + k0); v1 = *(const float4*)(pBh + k0 + 8);
        *(float4*)sBh_w = v0; *(float4*)(sBh_w + 8) = v1;
        v0 = *(const float4*)(pBl + k0); v1 = *(const float4*)(pBl + k0 + 8);
        *(float4*)sBl_w = v0; *(float4*)(sBl_w + 8) = v1;
        __syncthreads();

#pragma unroll
        for (int ks = 0; ks < 2; ks++) {
            uint32_t ah[2][4], al[2][4];
            ldm4(ah[0], bAh + ofsA[0] + ks * 32);
            ldm4(ah[1], bAh + ofsA[1] + ks * 32);
            ldm4(al[0], bAl + ofsA[0] + ks * 32);
            ldm4(al[1], bAl + ofsA[1] + ks * 32);
#pragma unroll
            for (int ng = 0; ng < 4; ng++) {
                uint32_t bh[4], bl[4];
                ldm4(bh, bBh + ofsB[ng] + ks * 32);
                ldm4(bl, bBl + ofsB[ng] + ks * 32);
#pragma unroll
                for (int mt = 0; mt < 2; mt++) {
                    float* d0 = acc[mt][2 * ng];
                    float* d1 = acc[mt][2 * ng + 1];
                    mma16816(d0, ah[mt], bh[0], bh[2]);
                    mma16816(d0, ah[mt], bl[0], bl[2]);
                    mma16816(d0, al[mt], bh[0], bh[2]);
                    mma16816(d1, ah[mt], bh[1], bh[3]);
                    mma16816(d1, ah[mt], bl[1], bl[3]);
                    mma16816(d1, al[mt], bh[1], bh[3]);
                }
            }
        }
        __syncthreads();
    }

    int gid = lane >> 2, tig = lane & 3;
#pragma unroll
    for (int mt = 0; mt < 2; mt++) {
        int row = m0 + mw * 32 + mt * 16 + gid;
#pragma unroll
        for (int nt = 0; nt < 8; nt++) {
            int col = nw * 64 + nt * 8 + tig * 2;
            float* p0 = Cacc + (size_t)row * OUTD + col;
            float* p1 = Cacc + (size_t)(row + 8) * OUTD + col;
            atomicAdd(p0,     acc[mt][nt][0]);
            atomicAdd(p0 + 1, acc[mt][nt][1]);
            atomicAdd(p1,     acc[mt][nt][2]);
            atomicAdd(p1 + 1, acc[mt][nt][3]);
        }
    }
}

// ---------------- GIN layer 0: projection p = x @ W1a (78-dim) --------------
__global__ void __launch_bounds__(256) proj78_kernel(
    const float* __restrict__ hin, const float* __restrict__ wa,
    float* __restrict__ p)
{
    __shared__ float wa_s[FXD * DIM];
    int tid = threadIdx.x;
    for (int i = tid; i < FXD * DIM; i += blockDim.x) wa_s[i] = wa[i];
    __syncthreads();

    int lane = tid & 31;
    int node = blockIdx.x * (blockDim.x >> 5) + (tid >> 5);
    if (node >= N_ATOMS) return;

    const float* row = hin + (size_t)node * FXD;
    float acc = 0.f;
#pragma unroll 4
    for (int c = 0; c < FXD; c++)
        acc = fmaf(__ldg(row + c), wa_s[c * DIM + lane], acc);
    p[node * DIM + lane] = acc;
}

// ---- layer 0 tail: gather p + y = relu(relu(t+ba)@Wb + bb) + BN stats ------
__global__ void __launch_bounds__(256) mlp2agg_kernel(
    const float* __restrict__ p, const float* __restrict__ wb,
    const float* __restrict__ ba, const float* __restrict__ bb,
    float* __restrict__ y, float* __restrict__ stats)
{
    __shared__ float wb_s[DIM * DIM];
    int tid = threadIdx.x;
    for (int i = tid; i < DIM * DIM; i += blockDim.x) wb_s[i] = wb[i];
    __syncthreads();

    int lane = tid & 31;
    int warpId = blockIdx.x * (blockDim.x >> 5) + (tid >> 5);
    int nWarps = gridDim.x * (blockDim.x >> 5);
    float bav = ba[lane], bbv = bb[lane];
    float s0 = 0.f, s1 = 0.f;

    for (int i = warpId; i < N_ATOMS; i += nWarps) {
        int rr = (lane < 2) ? g_rowptr[i + lane] : 0;
        int r0 = __shfl_sync(0xffffffffu, rr, 0);
        int r1 = __shfl_sync(0xffffffffu, rr, 1);

        float t = p[(size_t)i * DIM + lane];
        for (int base = r0; base < r1; base += 32) {
            int myE = base + lane;
            int s = (myE < r1) ? g_esorted[myE] : 0;
            int cnt = min(r1 - base, 32);
            for (int j = 0; j < cnt; j++) {
                int sj = __shfl_sync(0xffffffffu, s, j);
                t += p[(size_t)sj * DIM + lane];
            }
        }

        float hidden = fmaxf(t + bav, 0.f);
        float acc = bbv;
#pragma unroll
        for (int c = 0; c < DIM; c++) {
            float hv = __shfl_sync(0xffffffffu, hidden, c);
            acc = fmaf(hv, wb_s[c * DIM + lane], acc);
        }
        float yv = fmaxf(acc, 0.f);
        y[(size_t)i * DIM + lane] = yv;
        s0 += yv;
        s1 += yv * yv;
    }
    atomicAdd(&stats[lane], s0);
    atomicAdd(&stats[DIM + lane], s1);
}

// ====== fused full GIN layer (layers 1-4): BN fold + gather + MLP + stats ===
// input y_in is PRE-BN output of previous layer; BN of prev layer folded:
//   t = y_i + sum_j y_j  (deg+1 rows aggregated)
//   hidden = relu( t @ (sc.Wa) + ba + (deg+1)*(sh@Wa) )
//   out = relu(hidden @ Wb + bb);  accumulate stats of out.
__global__ void __launch_bounds__(256) ginfull_kernel(
    const float* __restrict__ y_in, const float* __restrict__ wa,
    const float* __restrict__ ba, const float* __restrict__ wb,
    const float* __restrict__ bb, const float* __restrict__ gamma,
    const float* __restrict__ beta, const float* __restrict__ statsIn,
    float* __restrict__ y_out, float* __restrict__ statsOut)
{
    __shared__ float wa_s[DIM * DIM], wb_s[DIM * DIM];
    __shared__ float sc_s[DIM], sh_s[DIM], shwa_s[DIM];
    int tid = threadIdx.x;
    if (tid < DIM) {
        float mu = statsIn[tid] * (1.0f / N_ATOMS);
        float var = statsIn[DIM + tid] * (1.0f / N_ATOMS) - mu * mu;
        float sc = gamma[tid] * rsqrtf(var + 1e-5f);
        sc_s[tid] = sc;
        sh_s[tid] = beta[tid] - mu * sc;
    }
    __syncthreads();
    for (int i = tid; i < DIM * DIM; i += blockDim.x) {
        wa_s[i] = sc_s[i >> 5] * wa[i];
        wb_s[i] = wb[i];
    }
    if (tid < DIM) {
        float acc = 0.f;
#pragma unroll
        for (int c = 0; c < DIM; c++) acc = fmaf(sh_s[c], wa[c * DIM + tid], acc);
        shwa_s[tid] = acc;
    }
    __syncthreads();

    int lane = tid & 31;
    int warpId = blockIdx.x * (blockDim.x >> 5) + (tid >> 5);
    int nWarps = gridDim.x * (blockDim.x >> 5);
    float bav = ba[lane], bbv = bb[lane], shwav = shwa_s[lane];
    float s0 = 0.f, s1 = 0.f;

    for (int i = warpId; i < N_ATOMS; i += nWarps) {
        int rr = (lane < 2) ? g_rowptr[i + lane] : 0;
        int r0 = __shfl_sync(0xffffffffu, rr, 0);
        int r1 = __shfl_sync(0xffffffffu, rr, 1);
        int deg1 = r1 - r0 + 1;

        float t = y_in[(size_t)i * DIM + lane];
        for (int base = r0; base < r1; base += 32) {
            int myE = base + lane;
            int s = (myE < r1) ? g_esorted[myE] : 0;
            int cnt = min(r1 - base, 32);
            for (int j = 0; j < cnt; j++) {
                int sj = __shfl_sync(0xffffffffu, s, j);
                t += y_in[(size_t)sj * DIM + lane];
            }
        }

        // matmul1 with BN-folded Wa and degree-corrected bias
        float h1 = fmaf((float)deg1, shwav, bav);
#pragma unroll
        for (int c = 0; c < DIM; c++) {
            float tv = __shfl_sync(0xffffffffu, t, c);
            h1 = fmaf(tv, wa_s[c * DIM + lane], h1);
        }
        float hidden = fmaxf(h1, 0.f);

        float acc = bbv;
#pragma unroll
        for (int c = 0; c < DIM; c++) {
            float hv = __shfl_sync(0xffffffffu, hidden, c);
            acc = fmaf(hv, wb_s[c * DIM + lane], acc);
        }
        float yv = fmaxf(acc, 0.f);
        y_out[(size_t)i * DIM + lane] = yv;
        s0 += yv;
        s1 += yv * yv;
    }
    atomicAdd(&statsOut[lane], s0);
    atomicAdd(&statsOut[DIM + lane], s1);
}

// ---------- global add pool (segmented, batch sorted, BN inline) ------------
__global__ void pool2_kernel(const float* __restrict__ y, const int* __restrict__ batch,
                             const float* __restrict__ statsIn,
                             const float* __restrict__ gamma, const float* __restrict__ beta,
                             float* __restrict__ xg)
{
    int lane = threadIdx.x & 31;
    int warp = (blockIdx.x * blockDim.x + threadIdx.x) >> 5;
    int nb = warp * 32;
    if (nb >= N_ATOMS) return;
    float mu = statsIn[lane] * (1.0f / N_ATOMS);
    float var = statsIn[DIM + lane] * (1.0f / N_ATOMS) - mu * mu;
    float sc = gamma[lane] * rsqrtf(var + 1e-5f);
    float sh = beta[lane] - mu * sc;

    int bt = (nb + lane < N_ATOMS) ? batch[nb + lane] : -1;
    int cur = __shfl_sync(0xffffffffu, bt, 0);
    float sum = 0.f;
    int last = min(32, N_ATOMS - nb);
    for (int j = 0; j < last; j++) {
        int b = __shfl_sync(0xffffffffu, bt, j);
        float v = fmaf(y[(size_t)(nb + j) * DIM + lane], sc, sh);
        if (b != cur) {
            atomicAdd(&xg[cur * DIM + lane], sum);
            sum = 0.f; cur = b;
        }
        sum += v;
    }
    atomicAdd(&xg[cur * DIM + lane], sum);
}

// -------- build xc: fc1_xd (cols 0..127) + LM copy (cols 256..2303) ---------
__global__ void xcfill_kernel(const float* __restrict__ xg, const float* __restrict__ w,
                              const float* __restrict__ bias,
                              const float* __restrict__ drug, const float* __restrict__ prot)
{
    int idx = blockIdx.x * blockDim.x + threadIdx.x;
    int total = BGR * (OUTD + 2 * LMDIM);
    if (idx >= total) return;
    int b = idx / (OUTD + 2 * LMDIM);
    int j = idx - b * (OUTD + 2 * LMDIM);
    float v;
    size_t d;
    if (j < OUTD) {
        float acc = bias[j];
#pragma unroll
        for (int c = 0; c < DIM; c++) acc = fmaf(xg[b * DIM + c], w[c * OUTD + j], acc);
        v = fmaxf(acc, 0.f);
        d = (size_t)b * COMB + j;
    } else {
        int jj = j - OUTD;
        v = (jj < LMDIM) ? drug[b * LMDIM + jj] : prot[b * LMDIM + (jj - LMDIM)];
        d = (size_t)b * COMB + 2 * OUTD + jj;
    }
    __half h, l; split16(v, h, l);
    g_XCh[d] = h; g_XCl[d] = l;
}

// ------------------------- conv LUT: M[k][f][v] ------------------------------
__global__ void lut_kernel(const float* __restrict__ emb, const float* __restrict__ w)
{
    int idx = blockIdx.x * blockDim.x + threadIdx.x;
    if (idx >= KW * NFLT * VOCAB) return;
    int v = idx % VOCAB;
    int f = (idx / VOCAB) % NFLT;
    int k = idx / (VOCAB * NFLT);
    float acc = 0.f;
#pragma unroll 4
    for (int c = 0; c < EMBD; c++)
        acc = fmaf(emb[v * EMBD + c], w[f * EMBD * KW + c * KW + k], acc);
    g_lut[idx] = acc;
}

// ------------- split-K epilogue: relu(acc+bias) -> fp16 hi/lo pair ----------
__global__ void epi16_kernel(const float* __restrict__ acc, const float* __restrict__ bias,
                             __half* __restrict__ Xh, __half* __restrict__ Xl,
                             int rows, int cols, int dstStride, int dstOff)
{
    int idx = blockIdx.x * blockDim.x + threadIdx.x;
    if (idx >= rows * cols) return;
    int r = idx / cols, c = idx - r * cols;
    float v = fmaxf(acc[idx] + bias[c], 0.f);
    __half h, l; split16(v, h, l);
    size_t d = (size_t)r * dstStride + dstOff + c;
    Xh[d] = h; Xl[d] = l;
}

// ---------------------- fp32 epilogue (h2) ----------------------------------
__global__ void epi_kernel(const float* __restrict__ acc, const float* __restrict__ bias,
                           float* __restrict__ dst, int rows, int cols)
{
    int idx = blockIdx.x * blockDim.x + threadIdx.x;
    if (idx >= rows * cols) return;
    int c = idx % cols;
    dst[idx] = fmaxf(acc[idx] + bias[c], 0.f);
}

// --------------------------- final output layer -----------------------------
__global__ void out_kernel(const float* __restrict__ h2, const float* __restrict__ w,
                           const float* __restrict__ b, float* __restrict__ out)
{
    int tid = threadIdx.x;
    int lane = tid & 31;
    int row = blockIdx.x * (blockDim.x >> 5) + (tid >> 5);
    if (row >= BGR) return;
    float acc = 0.f;
#pragma unroll
    for (int k = 0; k < H2DIM / 32; k++)
        acc = fmaf(h2[row * H2DIM + k * 32 + lane], w[k * 32 + lane], acc);
#pragma unroll
    for (int off = 16; off; off >>= 1) acc += __shfl_xor_sync(0xffffffffu, acc, off);
    if (lane == 0) out[row] = acc + b[0];
}

// ================================ launcher ===================================
extern "C" void kernel_launch(void* const* d_in, const int* in_sizes, int n_in,
                              void* d_out, int out_size)
{
    (void)in_sizes; (void)n_in; (void)out_size;
    const float* x        = (const float*)d_in[0];
    const int*   ei       = (const int*)d_in[1];
    const int*   batch    = (const int*)d_in[2];
    const int*   target   = (const int*)d_in[3];
    const float* drug_lm  = (const float*)d_in[4];
    const float* prot_lm  = (const float*)d_in[5];
    const float* w1a      = (const float*)d_in[6];
    const float* b1a      = (const float*)d_in[7];
    const float* w1b      = (const float*)d_in[8];
    const float* b1b      = (const float*)d_in[9];
    const float* gw_a     = (const float*)d_in[10];
    const float* gb_a     = (const float*)d_in[11];
    const float* gw_b     = (const float*)d_in[12];
    const float* gb_b     = (const float*)d_in[13];
    const float* bn_gamma = (const float*)d_in[14];
    const float* bn_beta  = (const float*)d_in[15];
    const float* fc1_xd_w = (const float*)d_in[16];
    const float* fc1_xd_b = (const float*)d_in[17];
    const float* emb      = (const float*)d_in[18];
    const float* convxt_w = (const float*)d_in[19];
    const float* convxt_b = (const float*)d_in[20];
    const float* fc1_xt_w = (const float*)d_in[21];
    const float* fc1_xt_b = (const float*)d_in[22];
    const float* fc1_w    = (const float*)d_in[23];
    const float* fc1_b    = (const float*)d_in[24];
    const float* fc2_w    = (const float*)d_in[25];
    const float* fc2_b    = (const float*)d_in[26];
    const float* out_w    = (const float*)d_in[27];
    const float* out_b    = (const float*)d_in[28];
    float* out = (float*)d_out;

    const int* srcp = ei;
    const int* dstp = ei + EDGES;

    void* vp;
    cudaGetSymbolAddress(&vp, g_p);      float* p_p     = (float*)vp;
    cudaGetSymbolAddress(&vp, g_y);      float* p_y     = (float*)vp;
    cudaGetSymbolAddress(&vp, g_y2);     float* p_y2    = (float*)vp;
    cudaGetSymbolAddress(&vp, g_stats);  float* p_stats = (float*)vp;
    cudaGetSymbolAddress(&vp, g_xg);     float* p_xg    = (float*)vp;
    cudaGetSymbolAddress(&vp, g_BxtH);   __half* p_BxtH = (__half*)vp;
    cudaGetSymbolAddress(&vp, g_BxtL);   __half* p_BxtL = (__half*)vp;
    cudaGetSymbolAddress(&vp, g_B1H);    __half* p_B1H  = (__half*)vp;
    cudaGetSymbolAddress(&vp, g_B1L);    __half* p_B1L  = (__half*)vp;
    cudaGetSymbolAddress(&vp, g_B2H);    __half* p_B2H  = (__half*)vp;
    cudaGetSymbolAddress(&vp, g_B2L);    __half* p_B2L  = (__half*)vp;
    cudaGetSymbolAddress(&vp, g_XCh);    __half* p_XCh  = (__half*)vp;
    cudaGetSymbolAddress(&vp, g_XCl);    __half* p_XCl  = (__half*)vp;
    cudaGetSymbolAddress(&vp, g_H1h);    __half* p_H1h  = (__half*)vp;
    cudaGetSymbolAddress(&vp, g_H1l);    __half* p_H1l  = (__half*)vp;
    cudaGetSymbolAddress(&vp, g_xtacc);  float* p_xtacc = (float*)vp;
    cudaGetSymbolAddress(&vp, g_h1acc);  float* p_h1acc = (float*)vp;
    cudaGetSymbolAddress(&vp, g_h2acc);  float* p_h2acc = (float*)vp;
    cudaGetSymbolAddress(&vp, g_h2);     float* p_h2    = (float*)vp;

    cudaFuncSetAttribute(cgemm, cudaFuncAttributeMaxDynamicSharedMemorySize, CG_TOTAL);

    // --- launches 1-4: zero, w16tx, lut, cgemm (cgemm = 4th for ncu capture)
    zero_kernel<<<512, 256>>>();
    { dim3 g(CONVL, OUTD / 32); w16tx_kernel<<<g, 256>>>(fc1_xt_w, p_BxtH, p_BxtL); }
    lut_kernel<<<(KW * NFLT * VOCAB + 255) / 256, 256>>>(emb, convxt_w);
    {
        dim3 grid(1, BGR / 128, SPLITS_XT);
        cgemm<<<grid, 256, CG_TOTAL>>>(target, convxt_b, p_BxtH, p_BxtL, p_xtacc);
    }
    epi16_kernel<<<(BGR * OUTD + 255) / 256, 256>>>(p_xtacc, fc1_xt_b, p_XCh, p_XCl,
                                                    BGR, OUTD, COMB, OUTD);

    // --- CSR build
    hist_kernel<<<(EDGES + 255) / 256, 256>>>(dstp);
    scan1_kernel<<<NB_SCAN, 256>>>();
    scan2_kernel<<<1, 512>>>();
    scan3_kernel<<<NB_SCAN, 256>>>();
    scatter_kernel<<<(EDGES + 255) / 256, 256>>>(srcp, dstp);

    // --- remaining weight conversions
    { dim3 g(COMB / 32, H1DIM / 32); w16t_kernel<<<g, 256>>>(fc1_w, p_B1H, p_B1L, COMB, H1DIM); }
    { dim3 g(H1DIM / 32, H2DIM / 32); w16t_kernel<<<g, 256>>>(fc2_w, p_B2H, p_B2L, H1DIM, H2DIM); }

    // --- GIN: layer 0 (proj78 + mlp2agg), layers 1-4 fused
    proj78_kernel<<<(N_ATOMS + 7) / 8, 256>>>(x, w1a, p_p);
    mlp2agg_kernel<<<512, 256>>>(p_p, w1b, b1a, b1b, p_y, p_stats);
    float* yin = p_y; float* yout = p_y2;
    for (int l = 1; l < 5; l++) {
        ginfull_kernel<<<512, 256>>>(yin,
            gw_a + (l - 1) * DIM * DIM, gb_a + (l - 1) * DIM,
            gw_b + (l - 1) * DIM * DIM, gb_b + (l - 1) * DIM,
            bn_gamma + (l - 1) * DIM, bn_beta + (l - 1) * DIM,
            p_stats + (l - 1) * 2 * DIM, yout, p_stats + l * 2 * DIM);
        float* tmp = yin; yin = yout; yout = tmp;
    }

    // --- pool (BN inline) + xc fill
    pool2_kernel<<<(N_ATOMS / 32 + 7) / 8, 256>>>(yin, batch,
        p_stats + 4 * 2 * DIM, bn_gamma + 4 * DIM, bn_beta + 4 * DIM, p_xg);
    xcfill_kernel<<<(BGR * (OUTD + 2 * LMDIM) + 255) / 256, 256>>>(
        p_xg, fc1_xd_w, fc1_xd_b, drug_lm, prot_lm);

    // --- head MLP
    {
        dim3 grid(H1DIM / 128, BGR / 128, 4);
        hgemm<<<grid, 256>>>(p_XCh, p_XCl, p_B1H, p_B1L, p_h1acc,
                             COMB, COMB, H1DIM, COMB / 32, 18);
    }
    epi16_kernel<<<(BGR * H1DIM + 255) / 256, 256>>>(p_h1acc, fc1_b, p_H1h, p_H1l,
                                                     BGR, H1DIM, H1DIM, 0);
    {
        dim3 grid(H2DIM / 128, BGR / 128, 16);
        hgemm<<<grid, 256>>>(p_H1h, p_H1l, p_B2H, p_B2L, p_h2acc,
                             H1DIM, H1DIM, H2DIM, H1DIM / 32, 2);
    }
    epi_kernel<<<(BGR * H2DIM + 255) / 256, 256>>>(p_h2acc, fc2_b, p_h2, BGR, H2DIM);
    out_kernel<<<BGR / 8, 256>>>(p_h2, out_w, out_b, out);
}